// round 11
// baseline (speedup 1.0000x reference)
#include <cuda_runtime.h>

#define HN 4096

constexpr int TH = 64;                     // output rows per warp-tile
constexpr int OUTW = 112;                  // output cols per warp strip
constexpr int NSTRIPS = 37;
constexpr int WPB = 4;
constexpr int NTILES = NSTRIPS * (HN / TH);   // 2368
constexpr int NBLK = NTILES / WPB;            // 592 = 4 * 148
constexpr int N_INT = 35 * 62;                // 2170 interior tiles

__device__ double g_accs[8 * 16];   // 8 slots, 128B apart; reset by last block
__device__ unsigned g_done;

static __device__ __forceinline__ float4 ld4p(const float* p, bool v) {
    float4 r = make_float4(0.f, 0.f, 0.f, 0.f);
    if (v) r = *reinterpret_cast<const float4*>(p);
    return r;
}

// 4-tap window sum over columns: g[c] = v[c-1]+v[c]+v[c+1]+v[c+2]
static __device__ __forceinline__ float4 hwin(float4 v, float vl, float vr0, float vr1) {
    float4 g;
    g.x = vl + v.x + v.y + v.z;
    g.y = g.x - vl + v.w;
    g.z = g.y - v.x + vr0;
    g.w = g.z - v.y + vr1;
    return g;
}

static __device__ __forceinline__ float maskf(float x, unsigned m) {
    return __uint_as_float(__float_as_uint(x) & m);
}

template<bool EDGE>
static __device__ __forceinline__ float tile_compute(
    const float* __restrict__ X, const float* __restrict__ Y,
    int strip, int tyt, int lane)
{
    const int ty0 = tyt * TH;
    const long col0 = (long)strip * OUTW - 8 + 4 * lane;
    const bool ld_ok = EDGE ? ((col0 >= 0) && (col0 + 3 < HN)) : true;
    const unsigned mCb = EDGE ? ((lane >= 1 && lane <= 30 && ld_ok) ? ~0u : 0u) : ~0u;
    const float mO = ((lane >= 2 && lane <= 29) && ld_ok) ? 1.f : 0.f;
    const float mOn = -mO;
    const int i0 = ty0 - 8;   // multiple of 4

    // pX/pY track the prefetch row (i+6) of the current step
    const float* pX = X + col0 + (long)(i0 + 6) * HN;
    const float* pY = Y + col0 + (long)(i0 + 6) * HN;

    // 2-deep prefetch, phase-rotated
    float4 xs[2], ys[2];
    {
        bool v4 = EDGE ? (ld_ok && (unsigned)(i0 + 4) < HN) : true;
        bool v5 = EDGE ? (ld_ok && (unsigned)(i0 + 5) < HN) : true;
        xs[0] = ld4p(pX - 2 * HN, v4); ys[0] = ld4p(pY - 2 * HN, v4);
        xs[1] = ld4p(pX - 1 * HN, v5); ys[1] = ld4p(pY - 1 * HN, v5);
    }

    // rings: raw rows (slot = row index & 3) and centered rows
    float4 rx[4], ry[4], rc1[4], rc2[4];
    float4 Vx, Vy, Vi, Vj, Vc;
    {
        float4 z = make_float4(0.f, 0.f, 0.f, 0.f);
#pragma unroll
        for (int s = 0; s < 4; ++s) { rx[s] = z; ry[s] = z; rc1[s] = z; rc2[s] = z; }
        Vx = Vy = Vi = Vj = Vc = z;
    }

    float acc = 0.f;   // accumulates -L over valid output pixels

// Core of one row-step: advance prefetch, rolling sums, centered values, sig sums.
// DO_OUT selects whether this step emits an output row (compile-time).
#define STEP(T, S, DO_OUT) do {                                                  \
    const int i = i0 + (T) + (S); (void)i;                                       \
    const int p_ = (S) & 1;                                                      \
    float4 xc = xs[p_], yc = ys[p_];                                             \
    {   bool v6 = EDGE ? (ld_ok && (unsigned)(i + 6) < HN) : true;               \
        xs[p_] = ld4p(pX, v6); ys[p_] = ld4p(pY, v6);                            \
        pX += HN; pY += HN; }                                                    \
    /* rolling vertical raw sums: +row(i+4), -row(i) (ring slot S) */            \
    {   float4 xo = rx[(S)]; rx[(S)] = xc;                                       \
        float4 yo = ry[(S)]; ry[(S)] = yc;                                       \
        Vx.x += xc.x - xo.x; Vx.y += xc.y - xo.y;                                \
        Vx.z += xc.z - xo.z; Vx.w += xc.w - xo.w;                                \
        Vy.x += yc.x - yo.x; Vy.y += yc.y - yo.y;                                \
        Vy.z += yc.z - yo.z; Vy.w += yc.w - yo.w; }                              \
    float4 x2 = rx[((S) + 2) & 3], y2 = ry[((S) + 2) & 3];  /* row i+2 */        \
    float vlx  = __shfl_up_sync(0xffffffffu, Vx.w, 1);                           \
    float vrx0 = __shfl_down_sync(0xffffffffu, Vx.x, 1);                         \
    float vrx1 = __shfl_down_sync(0xffffffffu, Vx.y, 1);                         \
    float vly  = __shfl_up_sync(0xffffffffu, Vy.w, 1);                           \
    float vry0 = __shfl_down_sync(0xffffffffu, Vy.x, 1);                         \
    float vry1 = __shfl_down_sync(0xffffffffu, Vy.y, 1);                         \
    float4 mx = hwin(Vx, vlx, vrx0, vrx1);   /* 16*mu at row i+2 */              \
    float4 my = hwin(Vy, vly, vry0, vry1);                                       \
    unsigned rmask = EDGE ? (((unsigned)(i + 2) < HN) ? mCb : 0u) : ~0u;         \
    float4 c1, c2;                                                               \
    c1.x = maskf(fmaf(mx.x, -0.0625f, x2.x), rmask);                             \
    c1.y = maskf(fmaf(mx.y, -0.0625f, x2.y), rmask);                             \
    c1.z = maskf(fmaf(mx.z, -0.0625f, x2.z), rmask);                             \
    c1.w = maskf(fmaf(mx.w, -0.0625f, x2.w), rmask);                             \
    c2.x = maskf(fmaf(my.x, -0.0625f, y2.x), rmask);                             \
    c2.y = maskf(fmaf(my.y, -0.0625f, y2.y), rmask);                             \
    c2.z = maskf(fmaf(my.z, -0.0625f, y2.z), rmask);                             \
    c2.w = maskf(fmaf(my.w, -0.0625f, y2.w), rmask);                             \
    /* rolling vertical sig sums over product rows i-1..i+2; ring stores c */    \
    {   const int sl = ((S) + 2) & 3;                                            \
        float4 o1 = rc1[sl], o2 = rc2[sl];                                       \
        rc1[sl] = c1; rc2[sl] = c2;                                              \
        Vi.x = fmaf(c1.x, c1.x, fmaf(o1.x, -o1.x, Vi.x));                        \
        Vi.y = fmaf(c1.y, c1.y, fmaf(o1.y, -o1.y, Vi.y));                        \
        Vi.z = fmaf(c1.z, c1.z, fmaf(o1.z, -o1.z, Vi.z));                        \
        Vi.w = fmaf(c1.w, c1.w, fmaf(o1.w, -o1.w, Vi.w));                        \
        Vj.x = fmaf(c2.x, c2.x, fmaf(o2.x, -o2.x, Vj.x));                        \
        Vj.y = fmaf(c2.y, c2.y, fmaf(o2.y, -o2.y, Vj.y));                        \
        Vj.z = fmaf(c2.z, c2.z, fmaf(o2.z, -o2.z, Vj.z));                        \
        Vj.w = fmaf(c2.w, c2.w, fmaf(o2.w, -o2.w, Vj.w));                        \
        Vc.x = fmaf(c1.x, c2.x, fmaf(o1.x, -o2.x, Vc.x));                        \
        Vc.y = fmaf(c1.y, c2.y, fmaf(o1.y, -o2.y, Vc.y));                        \
        Vc.z = fmaf(c1.z, c2.z, fmaf(o1.z, -o2.z, Vc.z));                        \
        Vc.w = fmaf(c1.w, c2.w, fmaf(o1.w, -o2.w, Vc.w));                        \
    }                                                                            \
    if (DO_OUT) {  /* compile-time: output row i */                              \
        float al  = __shfl_up_sync(0xffffffffu, Vi.w, 1);                        \
        float ar0 = __shfl_down_sync(0xffffffffu, Vi.x, 1);                      \
        float ar1 = __shfl_down_sync(0xffffffffu, Vi.y, 1);                      \
        float bl  = __shfl_up_sync(0xffffffffu, Vj.w, 1);                        \
        float br0 = __shfl_down_sync(0xffffffffu, Vj.x, 1);                      \
        float br1 = __shfl_down_sync(0xffffffffu, Vj.y, 1);                      \
        float cl  = __shfl_up_sync(0xffffffffu, Vc.w, 1);                        \
        float cr0 = __shfl_down_sync(0xffffffffu, Vc.x, 1);                      \
        float cr1 = __shfl_down_sync(0xffffffffu, Vc.y, 1);                      \
        float4 sii = hwin(Vi, al, ar0, ar1);                                     \
        float4 sjj = hwin(Vj, bl, br0, br1);                                     \
        float4 sij = hwin(Vc, cl, cr0, cr1);                                     \
        { float a = fmaxf(sii.x, 1e-20f), b = fmaxf(sjj.x, 1e-20f);              \
          float L = fmaxf(sij.x * rsqrtf(a * b), -1.f);                          \
          acc = fmaf(L, mOn, acc); }                                             \
        { float a = fmaxf(sii.y, 1e-20f), b = fmaxf(sjj.y, 1e-20f);              \
          float L = fmaxf(sij.y * rsqrtf(a * b), -1.f);                          \
          acc = fmaf(L, mOn, acc); }                                             \
        { float a = fmaxf(sii.z, 1e-20f), b = fmaxf(sjj.z, 1e-20f);              \
          float L = fmaxf(sij.z * rsqrtf(a * b), -1.f);                          \
          acc = fmaf(L, mOn, acc); }                                             \
        { float a = fmaxf(sii.w, 1e-20f), b = fmaxf(sjj.w, 1e-20f);              \
          float L = fmaxf(sij.w * rsqrtf(a * b), -1.f);                          \
          acc = fmaf(L, mOn, acc); }                                             \
    }                                                                            \
} while (0)

    // ---- warmup: 8 steps, no output, no per-step branch ----
    STEP(0, 0, false); STEP(0, 1, false); STEP(0, 2, false); STEP(0, 3, false);
    STEP(4, 0, false); STEP(4, 1, false); STEP(4, 2, false); STEP(4, 3, false);

    // ---- steady state: 64 steps, unconditional output ----
#pragma unroll 1
    for (int T = 8; T < TH + 8; T += 4) {
        STEP(T, 0, true);
        STEP(T, 1, true);
        STEP(T, 2, true);
        STEP(T, 3, true);
    }
#undef STEP

    // +1 per valid output pixel, plus accumulated (-L)
    return fmaf((float)(TH * 4), mO, acc);
}

__global__ void __launch_bounds__(WPB * 32, 5)
xcorr_kernel(const float* __restrict__ X, const float* __restrict__ Y,
             float* __restrict__ out) {
    const int lane = threadIdx.x & 31;
    const int warp = threadIdx.x >> 5;
    const int t = blockIdx.x * WPB + warp;   // 0..2367

    float tot;
    if (t < N_INT) {
        // interior tiles: strips 1..35, bands 1..62 — branch-free path
        const int strip = 1 + t % 35;
        const int band = 1 + t / 35;
        tot = tile_compute<false>(X, Y, strip, band, lane);
    } else {
        // edge tiles: band 0, band 63, strips 0 & 36
        const int e = t - N_INT;             // 0..197
        int strip, band;
        if (e < 37)      { strip = e;       band = 0; }
        else if (e < 74) { strip = e - 37;  band = 63; }
        else { int e2 = e - 74; strip = (e2 & 1) ? 36 : 0; band = 1 + (e2 >> 1); }
        tot = tile_compute<true>(X, Y, strip, band, lane);
    }

#pragma unroll
    for (int o = 16; o; o >>= 1) tot += __shfl_xor_sync(0xffffffffu, tot, o);

    __shared__ float wsum[WPB];
    if (lane == 0) wsum[warp] = tot;
    __syncthreads();
    if (threadIdx.x == 0) {
        float s = wsum[0] + wsum[1] + wsum[2] + wsum[3];
        atomicAdd(&g_accs[(blockIdx.x & 7) * 16], (double)s);
        __threadfence();
        unsigned done = atomicAdd(&g_done, 1u);
        if (done == (unsigned)(NBLK - 1)) {   // last block finalizes
            double m = 0.0;
#pragma unroll
            for (int k = 0; k < 8; ++k)
                m += atomicAdd(&g_accs[k * 16], 0.0);   // coherent read
            m *= (1.0 / ((double)HN * (double)HN));
            out[0] = (float)m;
            out[1] = (float)m;
#pragma unroll
            for (int k = 0; k < 8; ++k) g_accs[k * 16] = 0.0;  // reset for replay
            g_done = 0u;
        }
    }
}

extern "C" void kernel_launch(void* const* d_in, const int* in_sizes, int n_in,
                              void* d_out, int out_size) {
    const float* X = (const float*)d_in[0];   // outputs
    const float* Y = (const float*)d_in[1];   // labels
    xcorr_kernel<<<NBLK, WPB * 32>>>(X, Y, (float*)d_out);
}

// round 12
// speedup vs baseline: 1.3740x; 1.3740x over previous
#include <cuda_runtime.h>

#define HN 4096

constexpr int TH = 64;                     // output rows per warp-tile
constexpr int OUTW = 112;                  // output cols per warp strip
constexpr int NSTRIPS = 37;
constexpr int WPB = 4;
constexpr int NTILES = NSTRIPS * (HN / TH);   // 2368
constexpr int NBLK = NTILES / WPB;            // 592 = 4 * 148
constexpr int N_INT = 35 * 62;                // 2170 interior tiles

__device__ double g_accs[8 * 16];   // 8 slots, 128B apart; reset by last block
__device__ unsigned g_done;

static __device__ __forceinline__ float4 ld4p(const float* p, bool v) {
    float4 r = make_float4(0.f, 0.f, 0.f, 0.f);
    if (v) r = *reinterpret_cast<const float4*>(p);
    return r;
}

// 4-tap window sum over columns: g[c] = v[c-1]+v[c]+v[c+1]+v[c+2]
static __device__ __forceinline__ float4 hwin(float4 v, float vl, float vr0, float vr1) {
    float4 g;
    g.x = vl + v.x + v.y + v.z;
    g.y = g.x - vl + v.w;
    g.z = g.y - v.x + vr0;
    g.w = g.z - v.y + vr1;
    return g;
}

static __device__ __forceinline__ float maskf(float x, unsigned m) {
    return __uint_as_float(__float_as_uint(x) & m);
}

// pack 2 floats to bf16x2 (lo, hi); PTX cvt puts first src in high half
static __device__ __forceinline__ unsigned bf2pack(float lo, float hi) {
    unsigned r;
    asm("cvt.rn.bf16x2.f32 %0, %1, %2;" : "=r"(r) : "f"(hi), "f"(lo));
    return r;
}
static __device__ __forceinline__ float bf_lo(unsigned p) {
    return __uint_as_float(p << 16);
}
static __device__ __forceinline__ float bf_hi(unsigned p) {
    return __uint_as_float(p & 0xffff0000u);
}

template<bool EDGE>
static __device__ __forceinline__ float tile_compute(
    const float* __restrict__ X, const float* __restrict__ Y,
    int strip, int tyt, int lane)
{
    const int ty0 = tyt * TH;
    const long col0 = (long)strip * OUTW - 8 + 4 * lane;
    const bool ld_ok = EDGE ? ((col0 >= 0) && (col0 + 3 < HN)) : true;
    const unsigned mCb = EDGE ? ((lane >= 1 && lane <= 30 && ld_ok) ? ~0u : 0u) : ~0u;
    const float mO = ((lane >= 2 && lane <= 29) && ld_ok) ? 1.f : 0.f;
    const float mOn = -mO;
    const int i0 = ty0 - 8;   // multiple of 4

    // pX/pY track the prefetch row (i+6) of the current step
    const float* pX = X + col0 + (long)(i0 + 6) * HN;
    const float* pY = Y + col0 + (long)(i0 + 6) * HN;

    // 2-deep prefetch, phase-rotated
    float4 xs[2], ys[2];
    {
        bool v4 = EDGE ? (ld_ok && (unsigned)(i0 + 4) < HN) : true;
        bool v5 = EDGE ? (ld_ok && (unsigned)(i0 + 5) < HN) : true;
        xs[0] = ld4p(pX - 2 * HN, v4); ys[0] = ld4p(pY - 2 * HN, v4);
        xs[1] = ld4p(pX - 1 * HN, v5); ys[1] = ld4p(pY - 1 * HN, v5);
    }

    // raw-row rings (f32) and centered-row rings (bf16x2 packed: 2 regs/row/image)
    float4 rx[4], ry[4];
    unsigned pc1a[4], pc1b[4], pc2a[4], pc2b[4];
    float4 Vx, Vy, Vi, Vj, Vc;
    {
        float4 z = make_float4(0.f, 0.f, 0.f, 0.f);
#pragma unroll
        for (int s = 0; s < 4; ++s) {
            rx[s] = z; ry[s] = z;
            pc1a[s] = 0u; pc1b[s] = 0u; pc2a[s] = 0u; pc2b[s] = 0u;
        }
        Vx = Vy = Vi = Vj = Vc = z;
    }

    float acc = 0.f;   // accumulates -L over valid output pixels

#define STEP(T, S, DO_OUT) do {                                                  \
    const int i = i0 + (T) + (S); (void)i;                                       \
    const int p_ = (S) & 1;                                                      \
    float4 xc = xs[p_], yc = ys[p_];                                             \
    {   bool v6 = EDGE ? (ld_ok && (unsigned)(i + 6) < HN) : true;               \
        xs[p_] = ld4p(pX, v6); ys[p_] = ld4p(pY, v6);                            \
        pX += HN; pY += HN; }                                                    \
    /* rolling vertical raw sums: +row(i+4), -row(i) (ring slot S) */            \
    {   float4 xo = rx[(S)]; rx[(S)] = xc;                                       \
        float4 yo = ry[(S)]; ry[(S)] = yc;                                       \
        Vx.x += xc.x - xo.x; Vx.y += xc.y - xo.y;                                \
        Vx.z += xc.z - xo.z; Vx.w += xc.w - xo.w;                                \
        Vy.x += yc.x - yo.x; Vy.y += yc.y - yo.y;                                \
        Vy.z += yc.z - yo.z; Vy.w += yc.w - yo.w; }                              \
    float4 x2 = rx[((S) + 2) & 3], y2 = ry[((S) + 2) & 3];  /* row i+2 */        \
    float vlx  = __shfl_up_sync(0xffffffffu, Vx.w, 1);                           \
    float vrx0 = __shfl_down_sync(0xffffffffu, Vx.x, 1);                         \
    float vrx1 = __shfl_down_sync(0xffffffffu, Vx.y, 1);                         \
    float vly  = __shfl_up_sync(0xffffffffu, Vy.w, 1);                           \
    float vry0 = __shfl_down_sync(0xffffffffu, Vy.x, 1);                         \
    float vry1 = __shfl_down_sync(0xffffffffu, Vy.y, 1);                         \
    float4 mx = hwin(Vx, vlx, vrx0, vrx1);   /* 16*mu at row i+2 */              \
    float4 my = hwin(Vy, vly, vry0, vry1);                                       \
    unsigned rmask = EDGE ? (((unsigned)(i + 2) < HN) ? mCb : 0u) : ~0u;         \
    float4 c1, c2;                                                               \
    c1.x = maskf(fmaf(mx.x, -0.0625f, x2.x), rmask);                             \
    c1.y = maskf(fmaf(mx.y, -0.0625f, x2.y), rmask);                             \
    c1.z = maskf(fmaf(mx.z, -0.0625f, x2.z), rmask);                             \
    c1.w = maskf(fmaf(mx.w, -0.0625f, x2.w), rmask);                             \
    c2.x = maskf(fmaf(my.x, -0.0625f, y2.x), rmask);                             \
    c2.y = maskf(fmaf(my.y, -0.0625f, y2.y), rmask);                             \
    c2.z = maskf(fmaf(my.z, -0.0625f, y2.z), rmask);                             \
    c2.w = maskf(fmaf(my.w, -0.0625f, y2.w), rmask);                             \
    /* round c to bf16 ONCE; products use the rounded values on both the add    \
       and (4 steps later) the subtract side -> rolling sums stay exact */       \
    {   const int sl = ((S) + 2) & 3;                                            \
        unsigned nA = bf2pack(c1.x, c1.y), nB = bf2pack(c1.z, c1.w);             \
        unsigned mA = bf2pack(c2.x, c2.y), mB = bf2pack(c2.z, c2.w);             \
        unsigned oA = pc1a[sl], oB = pc1b[sl];                                   \
        unsigned uA = pc2a[sl], uB = pc2b[sl];                                   \
        pc1a[sl] = nA; pc1b[sl] = nB; pc2a[sl] = mA; pc2b[sl] = mB;              \
        float n1x = bf_lo(nA), n1y = bf_hi(nA), n1z = bf_lo(nB), n1w = bf_hi(nB);\
        float n2x = bf_lo(mA), n2y = bf_hi(mA), n2z = bf_lo(mB), n2w = bf_hi(mB);\
        float o1x = bf_lo(oA), o1y = bf_hi(oA), o1z = bf_lo(oB), o1w = bf_hi(oB);\
        float o2x = bf_lo(uA), o2y = bf_hi(uA), o2z = bf_lo(uB), o2w = bf_hi(uB);\
        Vi.x = fmaf(n1x, n1x, fmaf(o1x, -o1x, Vi.x));                            \
        Vi.y = fmaf(n1y, n1y, fmaf(o1y, -o1y, Vi.y));                            \
        Vi.z = fmaf(n1z, n1z, fmaf(o1z, -o1z, Vi.z));                            \
        Vi.w = fmaf(n1w, n1w, fmaf(o1w, -o1w, Vi.w));                            \
        Vj.x = fmaf(n2x, n2x, fmaf(o2x, -o2x, Vj.x));                            \
        Vj.y = fmaf(n2y, n2y, fmaf(o2y, -o2y, Vj.y));                            \
        Vj.z = fmaf(n2z, n2z, fmaf(o2z, -o2z, Vj.z));                            \
        Vj.w = fmaf(n2w, n2w, fmaf(o2w, -o2w, Vj.w));                            \
        Vc.x = fmaf(n1x, n2x, fmaf(o1x, -o2x, Vc.x));                            \
        Vc.y = fmaf(n1y, n2y, fmaf(o1y, -o2y, Vc.y));                            \
        Vc.z = fmaf(n1z, n2z, fmaf(o1z, -o2z, Vc.z));                            \
        Vc.w = fmaf(n1w, n2w, fmaf(o1w, -o2w, Vc.w));                            \
    }                                                                            \
    if (DO_OUT) {  /* compile-time: output row i */                              \
        float al  = __shfl_up_sync(0xffffffffu, Vi.w, 1);                        \
        float ar0 = __shfl_down_sync(0xffffffffu, Vi.x, 1);                      \
        float ar1 = __shfl_down_sync(0xffffffffu, Vi.y, 1);                      \
        float bl  = __shfl_up_sync(0xffffffffu, Vj.w, 1);                        \
        float br0 = __shfl_down_sync(0xffffffffu, Vj.x, 1);                      \
        float br1 = __shfl_down_sync(0xffffffffu, Vj.y, 1);                      \
        float cl  = __shfl_up_sync(0xffffffffu, Vc.w, 1);                        \
        float cr0 = __shfl_down_sync(0xffffffffu, Vc.x, 1);                      \
        float cr1 = __shfl_down_sync(0xffffffffu, Vc.y, 1);                      \
        float4 sii = hwin(Vi, al, ar0, ar1);                                     \
        float4 sjj = hwin(Vj, bl, br0, br1);                                     \
        float4 sij = hwin(Vc, cl, cr0, cr1);                                     \
        { float a = fmaxf(sii.x, 1e-20f), b = fmaxf(sjj.x, 1e-20f);              \
          float L = sij.x * rsqrtf(a * b);                                       \
          acc = fmaf(L, mOn, acc); }                                             \
        { float a = fmaxf(sii.y, 1e-20f), b = fmaxf(sjj.y, 1e-20f);              \
          float L = sij.y * rsqrtf(a * b);                                       \
          acc = fmaf(L, mOn, acc); }                                             \
        { float a = fmaxf(sii.z, 1e-20f), b = fmaxf(sjj.z, 1e-20f);              \
          float L = sij.z * rsqrtf(a * b);                                       \
          acc = fmaf(L, mOn, acc); }                                             \
        { float a = fmaxf(sii.w, 1e-20f), b = fmaxf(sjj.w, 1e-20f);              \
          float L = sij.w * rsqrtf(a * b);                                       \
          acc = fmaf(L, mOn, acc); }                                             \
    }                                                                            \
} while (0)

    // ---- warmup: 8 steps, no output, no per-step branch ----
    STEP(0, 0, false); STEP(0, 1, false); STEP(0, 2, false); STEP(0, 3, false);
    STEP(4, 0, false); STEP(4, 1, false); STEP(4, 2, false); STEP(4, 3, false);

    // ---- steady state: 64 steps, unconditional output ----
#pragma unroll 1
    for (int T = 8; T < TH + 8; T += 4) {
        STEP(T, 0, true);
        STEP(T, 1, true);
        STEP(T, 2, true);
        STEP(T, 3, true);
    }
#undef STEP

    // +1 per valid output pixel, plus accumulated (-L)
    return fmaf((float)(TH * 4), mO, acc);
}

__global__ void __launch_bounds__(WPB * 32, 4)
xcorr_kernel(const float* __restrict__ X, const float* __restrict__ Y,
             float* __restrict__ out) {
    const int lane = threadIdx.x & 31;
    const int warp = threadIdx.x >> 5;
    const int t = blockIdx.x * WPB + warp;   // 0..2367

    float tot;
    if (t < N_INT) {
        // interior tiles: strips 1..35, bands 1..62 — branch-free path
        const int strip = 1 + t % 35;
        const int band = 1 + t / 35;
        tot = tile_compute<false>(X, Y, strip, band, lane);
    } else {
        // edge tiles: band 0, band 63, strips 0 & 36
        const int e = t - N_INT;             // 0..197
        int strip, band;
        if (e < 37)      { strip = e;       band = 0; }
        else if (e < 74) { strip = e - 37;  band = 63; }
        else { int e2 = e - 74; strip = (e2 & 1) ? 36 : 0; band = 1 + (e2 >> 1); }
        tot = tile_compute<true>(X, Y, strip, band, lane);
    }

#pragma unroll
    for (int o = 16; o; o >>= 1) tot += __shfl_xor_sync(0xffffffffu, tot, o);

    __shared__ float wsum[WPB];
    if (lane == 0) wsum[warp] = tot;
    __syncthreads();
    if (threadIdx.x == 0) {
        float s = wsum[0] + wsum[1] + wsum[2] + wsum[3];
        atomicAdd(&g_accs[(blockIdx.x & 7) * 16], (double)s);
        __threadfence();
        unsigned done = atomicAdd(&g_done, 1u);
        if (done == (unsigned)(NBLK - 1)) {   // last block finalizes
            double m = 0.0;
#pragma unroll
            for (int k = 0; k < 8; ++k)
                m += atomicAdd(&g_accs[k * 16], 0.0);   // coherent read
            m *= (1.0 / ((double)HN * (double)HN));
            out[0] = (float)m;
            out[1] = (float)m;
#pragma unroll
            for (int k = 0; k < 8; ++k) g_accs[k * 16] = 0.0;  // reset for replay
            g_done = 0u;
        }
    }
}

extern "C" void kernel_launch(void* const* d_in, const int* in_sizes, int n_in,
                              void* d_out, int out_size) {
    const float* X = (const float*)d_in[0];   // outputs
    const float* Y = (const float*)d_in[1];   // labels
    xcorr_kernel<<<NBLK, WPB * 32>>>(X, Y, (float*)d_out);
}

// round 13
// speedup vs baseline: 1.6210x; 1.1797x over previous
#include <cuda_runtime.h>

#define HN 4096

constexpr int TH = 64;                     // output rows per warp-tile
constexpr int OUTW = 112;                  // output cols per warp strip
constexpr int NSTRIPS = 37;
constexpr int WPB = 4;
constexpr int NTILES = NSTRIPS * (HN / TH);   // 2368
constexpr int NBLK = NTILES / WPB;            // 592 = 4 * 148
constexpr int N_EDGE = 198;                   // edge tiles, spread 1-per-block

__device__ double g_accs[8 * 16];   // 8 slots, 128B apart; reset by last block
__device__ unsigned g_done;

static __device__ __forceinline__ float4 ld4p(const float* p, bool v) {
    float4 r = make_float4(0.f, 0.f, 0.f, 0.f);
    if (v) r = *reinterpret_cast<const float4*>(p);
    return r;
}

// 4-tap window sum over columns: g[c] = v[c-1]+v[c]+v[c+1]+v[c+2]
static __device__ __forceinline__ float4 hwin(float4 v, float vl, float vr0, float vr1) {
    float4 g;
    g.x = vl + v.x + v.y + v.z;
    g.y = g.x - vl + v.w;
    g.z = g.y - v.x + vr0;
    g.w = g.z - v.y + vr1;
    return g;
}

static __device__ __forceinline__ float maskf(float x, unsigned m) {
    return __uint_as_float(__float_as_uint(x) & m);
}

// pack two floats as bf16x2 (a -> lo half, b -> hi half)
static __device__ __forceinline__ unsigned bpack(float a, float b) {
    unsigned r;
    asm("cvt.rn.bf16x2.f32 %0, %1, %2;" : "=r"(r) : "f"(b), "f"(a));
    return r;
}
static __device__ __forceinline__ float bf_lo(unsigned p) {
    return __uint_as_float(p << 16);
}
static __device__ __forceinline__ float bf_hi(unsigned p) {
    return __uint_as_float(p & 0xffff0000u);
}

template<bool EDGE>
static __device__ __forceinline__ float tile_compute(
    const float* __restrict__ X, const float* __restrict__ Y,
    int strip, int tyt, int lane)
{
    const int ty0 = tyt * TH;
    const long col0 = (long)strip * OUTW - 8 + 4 * lane;
    const bool ld_ok = EDGE ? ((col0 >= 0) && (col0 + 3 < HN)) : true;
    const unsigned mCb = EDGE ? ((lane >= 1 && lane <= 30 && ld_ok) ? ~0u : 0u) : ~0u;
    const float mO = ((lane >= 2 && lane <= 29) && ld_ok) ? 1.f : 0.f;
    const float mOn = -mO;
    const int i0 = ty0 - 8;   // multiple of 4

    // pX/pY track the prefetch row (i+6) of the current step
    const float* pX = X + col0 + (long)(i0 + 6) * HN;
    const float* pY = Y + col0 + (long)(i0 + 6) * HN;

    // 2-deep prefetch, phase-rotated
    float4 xs[2], ys[2];
    {
        bool v4 = EDGE ? (ld_ok && (unsigned)(i0 + 4) < HN) : true;
        bool v5 = EDGE ? (ld_ok && (unsigned)(i0 + 5) < HN) : true;
        xs[0] = ld4p(pX - 2 * HN, v4); ys[0] = ld4p(pY - 2 * HN, v4);
        xs[1] = ld4p(pX - 1 * HN, v5); ys[1] = ld4p(pY - 1 * HN, v5);
    }

    // rings: raw rows (slot = row index & 3) and centered rows
    float4 rx[4], ry[4], rc1[4], rc2[4];
    float4 Vx, Vy, Vi, Vj, Vc;
    {
        float4 z = make_float4(0.f, 0.f, 0.f, 0.f);
#pragma unroll
        for (int s = 0; s < 4; ++s) { rx[s] = z; ry[s] = z; rc1[s] = z; rc2[s] = z; }
        Vx = Vy = Vi = Vj = Vc = z;
    }

    float acc = 0.f;   // accumulates -L over valid output pixels

#define STEP(T, S, DO_OUT) do {                                                  \
    const int i = i0 + (T) + (S); (void)i;                                       \
    const int p_ = (S) & 1;                                                      \
    float4 xc = xs[p_], yc = ys[p_];                                             \
    {   bool v6 = EDGE ? (ld_ok && (unsigned)(i + 6) < HN) : true;               \
        xs[p_] = ld4p(pX, v6); ys[p_] = ld4p(pY, v6);                            \
        pX += HN; pY += HN; }                                                    \
    /* rolling vertical raw sums: +row(i+4), -row(i) (ring slot S) */            \
    {   float4 xo = rx[(S)]; rx[(S)] = xc;                                       \
        float4 yo = ry[(S)]; ry[(S)] = yc;                                       \
        Vx.x += xc.x - xo.x; Vx.y += xc.y - xo.y;                                \
        Vx.z += xc.z - xo.z; Vx.w += xc.w - xo.w;                                \
        Vy.x += yc.x - yo.x; Vy.y += yc.y - yo.y;                                \
        Vy.z += yc.z - yo.z; Vy.w += yc.w - yo.w; }                              \
    float4 x2 = rx[((S) + 2) & 3], y2 = ry[((S) + 2) & 3];  /* row i+2 */        \
    /* packed boundary shuffles: (Vx,Vy) pairs in one bf16x2 payload */          \
    unsigned pw_ = bpack(Vx.w, Vy.w);                                            \
    unsigned pa_ = bpack(Vx.x, Vy.x);                                            \
    unsigned pb_ = bpack(Vx.y, Vy.y);                                            \
    unsigned sl_  = __shfl_up_sync(0xffffffffu, pw_, 1);                         \
    unsigned sr0_ = __shfl_down_sync(0xffffffffu, pa_, 1);                       \
    unsigned sr1_ = __shfl_down_sync(0xffffffffu, pb_, 1);                       \
    float4 mx = hwin(Vx, bf_lo(sl_), bf_lo(sr0_), bf_lo(sr1_));                  \
    float4 my = hwin(Vy, bf_hi(sl_), bf_hi(sr0_), bf_hi(sr1_));                  \
    unsigned rmask = EDGE ? (((unsigned)(i + 2) < HN) ? mCb : 0u) : ~0u;         \
    float4 c1, c2;                                                               \
    c1.x = maskf(fmaf(mx.x, -0.0625f, x2.x), rmask);                             \
    c1.y = maskf(fmaf(mx.y, -0.0625f, x2.y), rmask);                             \
    c1.z = maskf(fmaf(mx.z, -0.0625f, x2.z), rmask);                             \
    c1.w = maskf(fmaf(mx.w, -0.0625f, x2.w), rmask);                             \
    c2.x = maskf(fmaf(my.x, -0.0625f, y2.x), rmask);                             \
    c2.y = maskf(fmaf(my.y, -0.0625f, y2.y), rmask);                             \
    c2.z = maskf(fmaf(my.z, -0.0625f, y2.z), rmask);                             \
    c2.w = maskf(fmaf(my.w, -0.0625f, y2.w), rmask);                             \
    /* rolling vertical sig sums over product rows i-1..i+2; ring stores c */    \
    {   const int sl = ((S) + 2) & 3;                                            \
        float4 o1 = rc1[sl], o2 = rc2[sl];                                       \
        rc1[sl] = c1; rc2[sl] = c2;                                              \
        Vi.x = fmaf(c1.x, c1.x, fmaf(o1.x, -o1.x, Vi.x));                        \
        Vi.y = fmaf(c1.y, c1.y, fmaf(o1.y, -o1.y, Vi.y));                        \
        Vi.z = fmaf(c1.z, c1.z, fmaf(o1.z, -o1.z, Vi.z));                        \
        Vi.w = fmaf(c1.w, c1.w, fmaf(o1.w, -o1.w, Vi.w));                        \
        Vj.x = fmaf(c2.x, c2.x, fmaf(o2.x, -o2.x, Vj.x));                        \
        Vj.y = fmaf(c2.y, c2.y, fmaf(o2.y, -o2.y, Vj.y));                        \
        Vj.z = fmaf(c2.z, c2.z, fmaf(o2.z, -o2.z, Vj.z));                        \
        Vj.w = fmaf(c2.w, c2.w, fmaf(o2.w, -o2.w, Vj.w));                        \
        Vc.x = fmaf(c1.x, c2.x, fmaf(o1.x, -o2.x, Vc.x));                        \
        Vc.y = fmaf(c1.y, c2.y, fmaf(o1.y, -o2.y, Vc.y));                        \
        Vc.z = fmaf(c1.z, c2.z, fmaf(o1.z, -o2.z, Vc.z));                        \
        Vc.w = fmaf(c1.w, c2.w, fmaf(o1.w, -o2.w, Vc.w));                        \
    }                                                                            \
    if (DO_OUT) {  /* compile-time: output row i */                              \
        unsigned qw_ = bpack(Vi.w, Vj.w);                                        \
        unsigned qa_ = bpack(Vi.x, Vj.x);                                        \
        unsigned qb_ = bpack(Vi.y, Vj.y);                                        \
        unsigned tw_ = __shfl_up_sync(0xffffffffu, qw_, 1);                      \
        unsigned ta_ = __shfl_down_sync(0xffffffffu, qa_, 1);                    \
        unsigned tb_ = __shfl_down_sync(0xffffffffu, qb_, 1);                    \
        float cl  = __shfl_up_sync(0xffffffffu, Vc.w, 1);                        \
        float cr0 = __shfl_down_sync(0xffffffffu, Vc.x, 1);                      \
        float cr1 = __shfl_down_sync(0xffffffffu, Vc.y, 1);                      \
        float4 sii = hwin(Vi, bf_lo(tw_), bf_lo(ta_), bf_lo(tb_));               \
        float4 sjj = hwin(Vj, bf_hi(tw_), bf_hi(ta_), bf_hi(tb_));               \
        float4 sij = hwin(Vc, cl, cr0, cr1);                                     \
        { float a = fmaxf(sii.x, 1e-20f), b = fmaxf(sjj.x, 1e-20f);              \
          float L = sij.x * rsqrtf(a * b);                                       \
          acc = fmaf(L, mOn, acc); }                                             \
        { float a = fmaxf(sii.y, 1e-20f), b = fmaxf(sjj.y, 1e-20f);              \
          float L = sij.y * rsqrtf(a * b);                                       \
          acc = fmaf(L, mOn, acc); }                                             \
        { float a = fmaxf(sii.z, 1e-20f), b = fmaxf(sjj.z, 1e-20f);              \
          float L = sij.z * rsqrtf(a * b);                                       \
          acc = fmaf(L, mOn, acc); }                                             \
        { float a = fmaxf(sii.w, 1e-20f), b = fmaxf(sjj.w, 1e-20f);              \
          float L = sij.w * rsqrtf(a * b);                                       \
          acc = fmaf(L, mOn, acc); }                                             \
    }                                                                            \
} while (0)

    // ---- warmup: 8 steps, no output, no per-step branch ----
    STEP(0, 0, false); STEP(0, 1, false); STEP(0, 2, false); STEP(0, 3, false);
    STEP(4, 0, false); STEP(4, 1, false); STEP(4, 2, false); STEP(4, 3, false);

    // ---- steady state: 64 steps, unconditional output ----
#pragma unroll 1
    for (int T = 8; T < TH + 8; T += 4) {
        STEP(T, 0, true);
        STEP(T, 1, true);
        STEP(T, 2, true);
        STEP(T, 3, true);
    }
#undef STEP

    // +1 per valid output pixel, plus accumulated (-L)
    return fmaf((float)(TH * 4), mO, acc);
}

__global__ void __launch_bounds__(WPB * 32, 4)
xcorr_kernel(const float* __restrict__ X, const float* __restrict__ Y,
             float* __restrict__ out) {
    const int lane = threadIdx.x & 31;
    const int warp = threadIdx.x >> 5;
    const int b = blockIdx.x;

    float tot;
    if (warp == 3 && b < N_EDGE) {
        // one edge tile per early block -> edge work spread across all SMs
        const int e = b;                      // 0..197
        int strip, band;
        if (e < 37)      { strip = e;       band = 0; }
        else if (e < 74) { strip = e - 37;  band = 63; }
        else { int e2 = e - 74; strip = (e2 & 1) ? 36 : 0; band = 1 + (e2 >> 1); }
        tot = tile_compute<true>(X, Y, strip, band, lane);
    } else {
        // interior tiles: strips 1..35, bands 1..62 (2170 total)
        const int idx = (b < N_EDGE) ? (3 * b + warp) : (4 * b - N_EDGE + warp);
        const int strip = 1 + idx % 35;
        const int band = 1 + idx / 35;
        tot = tile_compute<false>(X, Y, strip, band, lane);
    }

#pragma unroll
    for (int o = 16; o; o >>= 1) tot += __shfl_xor_sync(0xffffffffu, tot, o);

    __shared__ float wsum[WPB];
    if (lane == 0) wsum[warp] = tot;
    __syncthreads();
    if (threadIdx.x == 0) {
        float s = wsum[0] + wsum[1] + wsum[2] + wsum[3];
        atomicAdd(&g_accs[(blockIdx.x & 7) * 16], (double)s);
        __threadfence();
        unsigned done = atomicAdd(&g_done, 1u);
        if (done == (unsigned)(NBLK - 1)) {   // last block finalizes
            double m = 0.0;
#pragma unroll
            for (int k = 0; k < 8; ++k)
                m += atomicAdd(&g_accs[k * 16], 0.0);   // coherent read
            m *= (1.0 / ((double)HN * (double)HN));
            out[0] = (float)m;
            out[1] = (float)m;
#pragma unroll
            for (int k = 0; k < 8; ++k) g_accs[k * 16] = 0.0;  // reset for replay
            g_done = 0u;
        }
    }
}

extern "C" void kernel_launch(void* const* d_in, const int* in_sizes, int n_in,
                              void* d_out, int out_size) {
    const float* X = (const float*)d_in[0];   // outputs
    const float* Y = (const float*)d_in[1];   // labels
    xcorr_kernel<<<NBLK, WPB * 32>>>(X, Y, (float*)d_out);
}